// round 14
// baseline (speedup 1.0000x reference)
#include <cuda_runtime.h>
#include <cuda_fp16.h>
#include <cstdint>

#define NNODES 100000
#define NEDGES 1600000
#define SCANB  ((NNODES + 255) / 256)    // 391 scan blocks

// ---- scratch (device globals; no allocation allowed) ----
__device__ int    g_counts[NNODES];      // zero at start of every exec (see scanC)
__device__ int    g_fill[NNODES];
__device__ int    g_rowptr[NNODES + 1];
__device__ int    g_partial[SCANB];
__device__ int2   g_edge[NEDGES];        // {src, __float_as_int(w)}
__device__ __half g_suph[(size_t)NNODES * 64];   // fp16 support (GEMM out, agg in)
__device__ float  g_h[(size_t)NNODES * 64];      // fp32 hidden state

// ---------------------------------------------------------------- CSR build
// 4 edges per thread, int4 load (NEDGES % 4 == 0)
__global__ void hist_kernel(const int* __restrict__ tgt) {
    int i = (blockIdx.x * blockDim.x + threadIdx.x) * 4;
    if (i >= NEDGES) return;
    int4 t = *(const int4*)&tgt[i];
    atomicAdd(&g_counts[t.x], 1);
    atomicAdd(&g_counts[t.y], 1);
    atomicAdd(&g_counts[t.z], 1);
    atomicAdd(&g_counts[t.w], 1);
}

__global__ void scanA_kernel() {
    __shared__ int s[256];
    int i = blockIdx.x * 256 + threadIdx.x;
    s[threadIdx.x] = (i < NNODES) ? g_counts[i] : 0;
    __syncthreads();
    for (int off = 128; off; off >>= 1) {
        if (threadIdx.x < off) s[threadIdx.x] += s[threadIdx.x + off];
        __syncthreads();
    }
    if (threadIdx.x == 0) g_partial[blockIdx.x] = s[0];
}

__global__ void scanB_kernel() {
    __shared__ int s[512];
    int t = threadIdx.x;
    s[t] = (t < SCANB) ? g_partial[t] : 0;
    __syncthreads();
    for (int off = 1; off < 512; off <<= 1) {
        int v = s[t];
        int add = (t >= off) ? s[t - off] : 0;
        __syncthreads();
        s[t] = v + add;
        __syncthreads();
    }
    if (t < SCANB) g_partial[t] = (t == 0) ? 0 : s[t - 1];   // exclusive
}

// per-block exclusive scan + base -> rowptr; zero fill AND counts (self-clean
// so the next graph replay's hist starts from zero without a memset launch).
__global__ void scanC_kernel() {
    __shared__ int s[256];
    int t = threadIdx.x;
    int i = blockIdx.x * 256 + t;
    int c = (i < NNODES) ? g_counts[i] : 0;
    s[t] = c;
    __syncthreads();
    for (int off = 1; off < 256; off <<= 1) {
        int v = s[t];
        int add = (t >= off) ? s[t - off] : 0;
        __syncthreads();
        s[t] = v + add;
        __syncthreads();
    }
    if (i < NNODES) {
        g_rowptr[i] = g_partial[blockIdx.x] + s[t] - c;   // exclusive
        g_fill[i]   = 0;
        g_counts[i] = 0;                                  // self-clean for next exec
    }
    if (i == 0) g_rowptr[NNODES] = NEDGES;
}

// 4 edges per thread, vectorized reads
__global__ void scatter_kernel(const int* __restrict__ src,
                               const int* __restrict__ tgt,
                               const float* __restrict__ w) {
    int i = (blockIdx.x * blockDim.x + threadIdx.x) * 4;
    if (i >= NEDGES) return;
    int4   s4 = *(const int4*)&src[i];
    int4   t4 = *(const int4*)&tgt[i];
    float4 w4 = *(const float4*)&w[i];
    int2 pk;
    int pos;
    pos = g_rowptr[t4.x] + atomicAdd(&g_fill[t4.x], 1);
    pk.x = s4.x; pk.y = __float_as_int(w4.x); g_edge[pos] = pk;
    pos = g_rowptr[t4.y] + atomicAdd(&g_fill[t4.y], 1);
    pk.x = s4.y; pk.y = __float_as_int(w4.y); g_edge[pos] = pk;
    pos = g_rowptr[t4.z] + atomicAdd(&g_fill[t4.z], 1);
    pk.x = s4.z; pk.y = __float_as_int(w4.z); g_edge[pos] = pk;
    pos = g_rowptr[t4.w] + atomicAdd(&g_fill[t4.w], 1);
    pk.x = s4.w; pk.y = __float_as_int(w4.w); g_edge[pos] = pk;
}

// ---------------------------------------------------------------- helpers
__device__ __forceinline__ unsigned smem_u32(const void* p) {
    return (unsigned)__cvta_generic_to_shared(p);
}
__device__ __forceinline__ void ldsm_x4(unsigned& a0, unsigned& a1,
                                        unsigned& a2, unsigned& a3, unsigned addr) {
    asm volatile("ldmatrix.sync.aligned.m8n8.x4.shared.b16 {%0,%1,%2,%3}, [%4];"
                 : "=r"(a0), "=r"(a1), "=r"(a2), "=r"(a3) : "r"(addr));
}
__device__ __forceinline__ void ldsm_x2t(unsigned& b0, unsigned& b1, unsigned addr) {
    asm volatile("ldmatrix.sync.aligned.m8n8.x2.trans.shared.b16 {%0,%1}, [%2];"
                 : "=r"(b0), "=r"(b1) : "r"(addr));
}
__device__ __forceinline__ void mma16816(float* c, unsigned a0, unsigned a1,
                                         unsigned a2, unsigned a3,
                                         unsigned b0, unsigned b1) {
    asm volatile(
        "mma.sync.aligned.m16n8k16.row.col.f32.f16.f16.f32 "
        "{%0,%1,%2,%3},{%4,%5,%6,%7},{%8,%9},{%0,%1,%2,%3};"
        : "+f"(c[0]), "+f"(c[1]), "+f"(c[2]), "+f"(c[3])
        : "r"(a0), "r"(a1), "r"(a2), "r"(a3), "r"(b0), "r"(b1));
}
__device__ __forceinline__ void h4_to_f4(uint2 u, float2& lo, float2& hi) {
    __half2 ha = *reinterpret_cast<__half2*>(&u.x);
    __half2 hb = *reinterpret_cast<__half2*>(&u.y);
    lo = __half22float2(ha);
    hi = __half22float2(hb);
}
// accumulate one edge {srcRow, w} into float4 acc from fp16 row base
__device__ __forceinline__ void edge_fma64(float4& a, const __half* suph,
                                           int srcRow, int sub, float w) {
    uint2 rv = *(const uint2*)&suph[(size_t)srcRow * 64 + sub * 4];
    float2 fa, fb; h4_to_f4(rv, fa, fb);
    a.x = fmaf(fa.x, w, a.x); a.y = fmaf(fa.y, w, a.y);
    a.z = fmaf(fb.x, w, a.z); a.w = fmaf(fb.y, w, a.w);
}

// ---------------------------------------------------------------- HMMA GEMM
// Yh[nrows,M] (fp16) = X[nrows,K] (fp32) @ W[K,M] (fp32) via fp16 HMMA.
template <int K, int M>
__global__ void gemm_kernel(const float* __restrict__ X,
                            const float* __restrict__ W,
                            __half* __restrict__ Yh, int nrows) {
    constexpr int KP = K + 8;
    constexpr int MP = M + 8;
    constexpr int NC = M / 8;
    extern __shared__ __half smh[];
    __half* Xs = smh;                   // [128][KP]
    __half* Ws = smh + 128 * KP;        // [K][MP]
    const int tid  = threadIdx.x;       // 256 threads
    const int wid  = tid >> 5;
    const int lane = tid & 31;
    const int rowBase = blockIdx.x * 128;

    for (int i = tid; i < 128 * (K / 2); i += 256) {
        int r = i / (K / 2), c2 = i % (K / 2);
        int grow = rowBase + r;
        float2 v = (grow < nrows) ? ((const float2*)X)[(size_t)grow * (K / 2) + c2]
                                  : make_float2(0.f, 0.f);
        *(__half2*)&Xs[r * KP + c2 * 2] = __floats2half2_rn(v.x, v.y);
    }
    for (int i = tid; i < K * (M / 2); i += 256) {
        int k = i / (M / 2), c2 = i % (M / 2);
        float2 v = ((const float2*)W)[i];
        *(__half2*)&Ws[k * MP + c2 * 2] = __floats2half2_rn(v.x, v.y);
    }
    __syncthreads();

    const int rw = wid * 16;
    float acc[NC][4];
#pragma unroll
    for (int nc = 0; nc < NC; nc++) {
#pragma unroll
        for (int q = 0; q < 4; q++) acc[nc][q] = 0.f;
    }

#pragma unroll
    for (int kc = 0; kc < K / 16; kc++) {
        unsigned a0, a1, a2, a3;
        unsigned aaddr = smem_u32(&Xs[(rw + (lane & 15)) * KP + kc * 16 + (lane >> 4) * 8]);
        ldsm_x4(a0, a1, a2, a3, aaddr);
#pragma unroll
        for (int nc = 0; nc < NC; nc++) {
            unsigned b0, b1;
            unsigned baddr = smem_u32(&Ws[(kc * 16 + (lane & 15)) * MP + nc * 8]);
            ldsm_x2t(b0, b1, baddr);
            mma16816(acc[nc], a0, a1, a2, a3, b0, b1);
        }
    }

    int rA = rowBase + rw + (lane >> 2);
    int rB = rA + 8;
    int colb = (lane & 3) * 2;
#pragma unroll
    for (int nc = 0; nc < NC; nc++) {
        int col = nc * 8 + colb;
        if (rA < nrows)
            *(__half2*)&Yh[(size_t)rA * M + col] = __floats2half2_rn(acc[nc][0], acc[nc][1]);
        if (rB < nrows)
            *(__half2*)&Yh[(size_t)rB * M + col] = __floats2half2_rn(acc[nc][2], acc[nc][3]);
    }
}

// ----------------------------------------------------- sparse aggregation, M=64
// TWO nodes per warp; lane owns 4 features (one 8B fp16 gather = full row is
// ONE 128B line). 8-edge main loop with int4 edge loads (2 edges / 16B).
__global__ void agg64_kernel(const __half* __restrict__ suph,
                             const float* __restrict__ bias,
                             float* hout, const float* resid, int has_resid) {
    int gw   = (blockIdx.x * blockDim.x + threadIdx.x) >> 5;
    int lane = threadIdx.x & 31;
    int hf   = lane >> 4, sub = lane & 15;
    int node = gw * 2 + hf;
    if (node >= NNODES) return;
    int e   = g_rowptr[node];
    int end = g_rowptr[node + 1];
    float4 a = make_float4(0.f, 0.f, 0.f, 0.f);
    // peel to even e for 16B-aligned int4 edge loads
    if ((e & 1) && e < end) {
        int2 ed = g_edge[e];
        edge_fma64(a, suph, ed.x, sub, __int_as_float(ed.y));
        e++;
    }
    for (; e + 8 <= end; e += 8) {
        int4 p0 = *(const int4*)&g_edge[e];
        int4 p1 = *(const int4*)&g_edge[e + 2];
        int4 p2 = *(const int4*)&g_edge[e + 4];
        int4 p3 = *(const int4*)&g_edge[e + 6];
        uint2 r0 = *(const uint2*)&suph[(size_t)p0.x * 64 + sub * 4];
        uint2 r1 = *(const uint2*)&suph[(size_t)p0.z * 64 + sub * 4];
        uint2 r2 = *(const uint2*)&suph[(size_t)p1.x * 64 + sub * 4];
        uint2 r3 = *(const uint2*)&suph[(size_t)p1.z * 64 + sub * 4];
        uint2 r4 = *(const uint2*)&suph[(size_t)p2.x * 64 + sub * 4];
        uint2 r5 = *(const uint2*)&suph[(size_t)p2.z * 64 + sub * 4];
        uint2 r6 = *(const uint2*)&suph[(size_t)p3.x * 64 + sub * 4];
        uint2 r7 = *(const uint2*)&suph[(size_t)p3.z * 64 + sub * 4];
        float2 fa, fb; float w;
        w = __int_as_float(p0.y); h4_to_f4(r0, fa, fb);
        a.x = fmaf(fa.x, w, a.x); a.y = fmaf(fa.y, w, a.y);
        a.z = fmaf(fb.x, w, a.z); a.w = fmaf(fb.y, w, a.w);
        w = __int_as_float(p0.w); h4_to_f4(r1, fa, fb);
        a.x = fmaf(fa.x, w, a.x); a.y = fmaf(fa.y, w, a.y);
        a.z = fmaf(fb.x, w, a.z); a.w = fmaf(fb.y, w, a.w);
        w = __int_as_float(p1.y); h4_to_f4(r2, fa, fb);
        a.x = fmaf(fa.x, w, a.x); a.y = fmaf(fa.y, w, a.y);
        a.z = fmaf(fb.x, w, a.z); a.w = fmaf(fb.y, w, a.w);
        w = __int_as_float(p1.w); h4_to_f4(r3, fa, fb);
        a.x = fmaf(fa.x, w, a.x); a.y = fmaf(fa.y, w, a.y);
        a.z = fmaf(fb.x, w, a.z); a.w = fmaf(fb.y, w, a.w);
        w = __int_as_float(p2.y); h4_to_f4(r4, fa, fb);
        a.x = fmaf(fa.x, w, a.x); a.y = fmaf(fa.y, w, a.y);
        a.z = fmaf(fb.x, w, a.z); a.w = fmaf(fb.y, w, a.w);
        w = __int_as_float(p2.w); h4_to_f4(r5, fa, fb);
        a.x = fmaf(fa.x, w, a.x); a.y = fmaf(fa.y, w, a.y);
        a.z = fmaf(fb.x, w, a.z); a.w = fmaf(fb.y, w, a.w);
        w = __int_as_float(p3.y); h4_to_f4(r6, fa, fb);
        a.x = fmaf(fa.x, w, a.x); a.y = fmaf(fa.y, w, a.y);
        a.z = fmaf(fb.x, w, a.z); a.w = fmaf(fb.y, w, a.w);
        w = __int_as_float(p3.w); h4_to_f4(r7, fa, fb);
        a.x = fmaf(fa.x, w, a.x); a.y = fmaf(fa.y, w, a.y);
        a.z = fmaf(fb.x, w, a.z); a.w = fmaf(fb.y, w, a.w);
    }
    for (; e < end; e++) {
        int2 ed = g_edge[e];
        edge_fma64(a, suph, ed.x, sub, __int_as_float(ed.y));
    }
    float4 bv = ((const float4*)bias)[sub];
    a.x = fmaxf(a.x + bv.x, 0.f);
    a.y = fmaxf(a.y + bv.y, 0.f);
    a.z = fmaxf(a.z + bv.z, 0.f);
    a.w = fmaxf(a.w + bv.w, 0.f);
    if (has_resid) {               // resid may alias hout: same-element RMW only
        float4 rv = ((const float4*)(resid + (size_t)node * 64))[sub];
        a.x += rv.x; a.y += rv.y; a.z += rv.z; a.w += rv.w;
    }
    ((float4*)(hout + (size_t)node * 64))[sub] = a;
}

// ------------------------------------------- sparse aggregation + log_softmax, M=40
__global__ void agg40_kernel(const __half* __restrict__ suph,
                             const float* __restrict__ bias,
                             float* __restrict__ out) {
    int gw   = (blockIdx.x * blockDim.x + threadIdx.x) >> 5;
    int lane = threadIdx.x & 31;
    int hf   = lane >> 4, sub = lane & 15;
    int node = gw * 2 + hf;
    if (node >= NNODES) return;
    const bool act = (sub < 10);
    int e   = g_rowptr[node];
    int end = g_rowptr[node + 1];
    float4 a = make_float4(0.f, 0.f, 0.f, 0.f);
    if ((e & 1) && e < end) {
        int2 ed = g_edge[e];
        uint2 rv = make_uint2(0, 0);
        if (act) rv = *(const uint2*)&suph[(size_t)ed.x * 40 + sub * 4];
        float w = __int_as_float(ed.y);
        float2 fa, fb; h4_to_f4(rv, fa, fb);
        a.x = fmaf(fa.x, w, a.x); a.y = fmaf(fa.y, w, a.y);
        a.z = fmaf(fb.x, w, a.z); a.w = fmaf(fb.y, w, a.w);
        e++;
    }
    for (; e + 4 <= end; e += 4) {
        int4 p0 = *(const int4*)&g_edge[e];
        int4 p1 = *(const int4*)&g_edge[e + 2];
        uint2 r0 = make_uint2(0, 0), r1 = r0, r2 = r0, r3 = r0;
        if (act) {
            r0 = *(const uint2*)&suph[(size_t)p0.x * 40 + sub * 4];
            r1 = *(const uint2*)&suph[(size_t)p0.z * 40 + sub * 4];
            r2 = *(const uint2*)&suph[(size_t)p1.x * 40 + sub * 4];
            r3 = *(const uint2*)&suph[(size_t)p1.z * 40 + sub * 4];
        }
        float2 fa, fb; float w;
        w = __int_as_float(p0.y); h4_to_f4(r0, fa, fb);
        a.x = fmaf(fa.x, w, a.x); a.y = fmaf(fa.y, w, a.y);
        a.z = fmaf(fb.x, w, a.z); a.w = fmaf(fb.y, w, a.w);
        w = __int_as_float(p0.w); h4_to_f4(r1, fa, fb);
        a.x = fmaf(fa.x, w, a.x); a.y = fmaf(fa.y, w, a.y);
        a.z = fmaf(fb.x, w, a.z); a.w = fmaf(fb.y, w, a.w);
        w = __int_as_float(p1.y); h4_to_f4(r2, fa, fb);
        a.x = fmaf(fa.x, w, a.x); a.y = fmaf(fa.y, w, a.y);
        a.z = fmaf(fb.x, w, a.z); a.w = fmaf(fb.y, w, a.w);
        w = __int_as_float(p1.w); h4_to_f4(r3, fa, fb);
        a.x = fmaf(fa.x, w, a.x); a.y = fmaf(fa.y, w, a.y);
        a.z = fmaf(fb.x, w, a.z); a.w = fmaf(fb.y, w, a.w);
    }
    for (; e < end; e++) {
        int2 ed = g_edge[e];
        uint2 rv = make_uint2(0, 0);
        if (act) rv = *(const uint2*)&suph[(size_t)ed.x * 40 + sub * 4];
        float w = __int_as_float(ed.y);
        float2 fa, fb; h4_to_f4(rv, fa, fb);
        a.x = fmaf(fa.x, w, a.x); a.y = fmaf(fa.y, w, a.y);
        a.z = fmaf(fb.x, w, a.z); a.w = fmaf(fb.y, w, a.w);
    }
    if (act) {
        float4 bv = ((const float4*)bias)[sub];
        a.x += bv.x; a.y += bv.y; a.z += bv.z; a.w += bv.w;
    }

    float m = act ? fmaxf(fmaxf(a.x, a.y), fmaxf(a.z, a.w)) : -3.4e38f;
#pragma unroll
    for (int o = 8; o; o >>= 1) m = fmaxf(m, __shfl_xor_sync(0xffffffffu, m, o, 16));
    float ssum = act ? (__expf(a.x - m) + __expf(a.y - m) +
                        __expf(a.z - m) + __expf(a.w - m)) : 0.f;
#pragma unroll
    for (int o = 8; o; o >>= 1) ssum += __shfl_xor_sync(0xffffffffu, ssum, o, 16);
    float L = m + __logf(ssum);

    if (act) {
        float4 o4; o4.x = a.x - L; o4.y = a.y - L; o4.z = a.z - L; o4.w = a.w - L;
        ((float4*)(out + (size_t)node * 40))[sub] = o4;
    }
}

// ---------------------------------------------------------------- launch
extern "C" void kernel_launch(void* const* d_in, const int* in_sizes, int n_in,
                              void* d_out, int out_size) {
    const float* x   = (const float*)d_in[0];
    const int*   src = (const int*)d_in[1];
    const int*   tgt = (const int*)d_in[2];
    const float* mw  = (const float*)d_in[3];
    const float* W0  = (const float*)d_in[4];  const float* b0 = (const float*)d_in[5];
    const float* W1  = (const float*)d_in[6];  const float* b1 = (const float*)d_in[7];
    const float* W2  = (const float*)d_in[8];  const float* b2 = (const float*)d_in[9];
    const float* W3  = (const float*)d_in[10]; const float* b3 = (const float*)d_in[11];
    float* out = (float*)d_out;

    const int S0 = (128 * 136 + 128 * 72) * 2;   // 53248 (opt-in)
    const int S1 = (128 * 72 + 64 * 72) * 2;     // 27648
    const int S3 = (128 * 72 + 64 * 48) * 2;     // 24576
    cudaFuncSetAttribute(gemm_kernel<128, 64>, cudaFuncAttributeMaxDynamicSharedMemorySize, S0);

    void* p;
    cudaGetSymbolAddress(&p, g_suph);  __half* sup = (__half*)p;
    cudaGetSymbolAddress(&p, g_h);     float*  h   = (float*)p;

    // ---- CSR build (counts pre-zeroed: static init on exec 1, scanC self-clean after) ----
    hist_kernel<<<(NEDGES / 4 + 255) / 256, 256>>>(tgt);
    scanA_kernel<<<SCANB, 256>>>();
    scanB_kernel<<<1, 512>>>();
    scanC_kernel<<<SCANB, 256>>>();
    scatter_kernel<<<(NEDGES / 4 + 255) / 256, 256>>>(src, tgt, mw);

    const int gblocks  = (NNODES + 127) / 128;
    const int a2blocks = (((NNODES + 1) / 2) * 32 + 255) / 256;   // 2 nodes/warp

    // layer 0: h = relu(A @ (x W0) + b0)
    gemm_kernel<128, 64><<<gblocks, 256, S0>>>(x, W0, sup, NNODES);
    agg64_kernel<<<a2blocks, 256>>>(sup, b0, h, nullptr, 0);
    // layer 1: h = relu(A @ (h W1) + b1) + h
    gemm_kernel<64, 64><<<gblocks, 256, S1>>>(h, W1, sup, NNODES);
    agg64_kernel<<<a2blocks, 256>>>(sup, b1, h, h, 1);
    // layer 2
    gemm_kernel<64, 64><<<gblocks, 256, S1>>>(h, W2, sup, NNODES);
    agg64_kernel<<<a2blocks, 256>>>(sup, b2, h, h, 1);
    // layer 3: out = log_softmax(A @ (h W3) + b3)
    gemm_kernel<64, 40><<<gblocks, 256, S3>>>(h, W3, sup, NNODES);
    agg40_kernel<<<a2blocks, 256>>>(sup, b3, out);
}

// round 15
// speedup vs baseline: 1.0172x; 1.0172x over previous
#include <cuda_runtime.h>
#include <cuda_fp16.h>
#include <cstdint>

#define NNODES 100000
#define NEDGES 1600000
#define SCANB  ((NNODES + 255) / 256)    // 391 scan blocks

// ---- scratch (device globals; no allocation allowed) ----
__device__ int    g_counts[NNODES];      // zero before hist: static init (exec 1),
                                         // then scanC self-clean (later execs)
__device__ int    g_fill[NNODES];        // scanC sets to rowptr[i]; scatter bumps
__device__ int    g_rowptr[NNODES + 1];
__device__ int    g_partial[SCANB];
__device__ int2   g_edge[NEDGES];        // {src, __float_as_int(w)}
__device__ __half g_suph[(size_t)NNODES * 64];   // fp16 support (GEMM out, agg in)
__device__ float  g_h[(size_t)NNODES * 64];      // fp32 hidden state

// ---------------------------------------------------------------- CSR build
__global__ void hist_kernel(const int* __restrict__ tgt) {
    int e = blockIdx.x * blockDim.x + threadIdx.x;
    if (e < NEDGES) atomicAdd(&g_counts[tgt[e]], 1);
}

__global__ void scanA_kernel() {
    __shared__ int s[256];
    int i = blockIdx.x * 256 + threadIdx.x;
    s[threadIdx.x] = (i < NNODES) ? g_counts[i] : 0;
    __syncthreads();
    for (int off = 128; off; off >>= 1) {
        if (threadIdx.x < off) s[threadIdx.x] += s[threadIdx.x + off];
        __syncthreads();
    }
    if (threadIdx.x == 0) g_partial[blockIdx.x] = s[0];
}

__global__ void scanB_kernel() {
    __shared__ int s[512];
    int t = threadIdx.x;
    s[t] = (t < SCANB) ? g_partial[t] : 0;
    __syncthreads();
    for (int off = 1; off < 512; off <<= 1) {
        int v = s[t];
        int add = (t >= off) ? s[t - off] : 0;
        __syncthreads();
        s[t] = v + add;
        __syncthreads();
    }
    if (t < SCANB) g_partial[t] = (t == 0) ? 0 : s[t - 1];   // exclusive
}

// per-block exclusive scan + base -> rowptr; g_fill seeded with rowptr so the
// scatter needs NO rowptr load; g_counts self-cleaned for the next execution.
__global__ void scanC_kernel() {
    __shared__ int s[256];
    int t = threadIdx.x;
    int i = blockIdx.x * 256 + t;
    int c = (i < NNODES) ? g_counts[i] : 0;
    s[t] = c;
    __syncthreads();
    for (int off = 1; off < 256; off <<= 1) {
        int v = s[t];
        int add = (t >= off) ? s[t - off] : 0;
        __syncthreads();
        s[t] = v + add;
        __syncthreads();
    }
    if (i < NNODES) {
        int rp = g_partial[blockIdx.x] + s[t] - c;   // exclusive prefix
        g_rowptr[i] = rp;
        g_fill[i]   = rp;                            // scatter cursor = rowptr
        g_counts[i] = 0;                             // self-clean for next exec
    }
    if (i == 0) g_rowptr[NNODES] = NEDGES;
}

// single atomic per edge; no rowptr load (cursor pre-seeded in scanC)
__global__ void scatter_kernel(const int* __restrict__ src,
                               const int* __restrict__ tgt,
                               const float* __restrict__ w) {
    int e = blockIdx.x * blockDim.x + threadIdx.x;
    if (e >= NEDGES) return;
    int pos = atomicAdd(&g_fill[tgt[e]], 1);
    int2 pk; pk.x = src[e]; pk.y = __float_as_int(w[e]);
    g_edge[pos] = pk;                     // single 8B store
}

// ---------------------------------------------------------------- helpers
__device__ __forceinline__ unsigned smem_u32(const void* p) {
    return (unsigned)__cvta_generic_to_shared(p);
}
__device__ __forceinline__ void ldsm_x4(unsigned& a0, unsigned& a1,
                                        unsigned& a2, unsigned& a3, unsigned addr) {
    asm volatile("ldmatrix.sync.aligned.m8n8.x4.shared.b16 {%0,%1,%2,%3}, [%4];"
                 : "=r"(a0), "=r"(a1), "=r"(a2), "=r"(a3) : "r"(addr));
}
__device__ __forceinline__ void ldsm_x2t(unsigned& b0, unsigned& b1, unsigned addr) {
    asm volatile("ldmatrix.sync.aligned.m8n8.x2.trans.shared.b16 {%0,%1}, [%2];"
                 : "=r"(b0), "=r"(b1) : "r"(addr));
}
__device__ __forceinline__ void mma16816(float* c, unsigned a0, unsigned a1,
                                         unsigned a2, unsigned a3,
                                         unsigned b0, unsigned b1) {
    asm volatile(
        "mma.sync.aligned.m16n8k16.row.col.f32.f16.f16.f32 "
        "{%0,%1,%2,%3},{%4,%5,%6,%7},{%8,%9},{%0,%1,%2,%3};"
        : "+f"(c[0]), "+f"(c[1]), "+f"(c[2]), "+f"(c[3])
        : "r"(a0), "r"(a1), "r"(a2), "r"(a3), "r"(b0), "r"(b1));
}
__device__ __forceinline__ void h4_to_f4(uint2 u, float2& lo, float2& hi) {
    __half2 ha = *reinterpret_cast<__half2*>(&u.x);
    __half2 hb = *reinterpret_cast<__half2*>(&u.y);
    lo = __half22float2(ha);
    hi = __half22float2(hb);
}

// ---------------------------------------------------------------- HMMA GEMM
// Yh[nrows,M] (fp16) = X[nrows,K] (fp32) @ W[K,M] (fp32) via fp16 HMMA,
// fp32 accumulate. 128-row block tile, 8 warps; warp = 16 rows x M cols.
template <int K, int M>
__global__ void gemm_kernel(const float* __restrict__ X,
                            const float* __restrict__ W,
                            __half* __restrict__ Yh, int nrows) {
    constexpr int KP = K + 8;           // padded X row (halfs)
    constexpr int MP = M + 8;           // padded W row (halfs)
    constexpr int NC = M / 8;           // n-chunks per warp
    extern __shared__ __half smh[];
    __half* Xs = smh;                   // [128][KP]
    __half* Ws = smh + 128 * KP;        // [K][MP]
    const int tid  = threadIdx.x;       // 256 threads
    const int wid  = tid >> 5;
    const int lane = tid & 31;
    const int rowBase = blockIdx.x * 128;

    for (int i = tid; i < 128 * (K / 2); i += 256) {
        int r = i / (K / 2), c2 = i % (K / 2);
        int grow = rowBase + r;
        float2 v = (grow < nrows) ? ((const float2*)X)[(size_t)grow * (K / 2) + c2]
                                  : make_float2(0.f, 0.f);
        *(__half2*)&Xs[r * KP + c2 * 2] = __floats2half2_rn(v.x, v.y);
    }
    for (int i = tid; i < K * (M / 2); i += 256) {
        int k = i / (M / 2), c2 = i % (M / 2);
        float2 v = ((const float2*)W)[i];
        *(__half2*)&Ws[k * MP + c2 * 2] = __floats2half2_rn(v.x, v.y);
    }
    __syncthreads();

    const int rw = wid * 16;
    float acc[NC][4];
#pragma unroll
    for (int nc = 0; nc < NC; nc++) {
#pragma unroll
        for (int q = 0; q < 4; q++) acc[nc][q] = 0.f;
    }

#pragma unroll
    for (int kc = 0; kc < K / 16; kc++) {
        unsigned a0, a1, a2, a3;
        unsigned aaddr = smem_u32(&Xs[(rw + (lane & 15)) * KP + kc * 16 + (lane >> 4) * 8]);
        ldsm_x4(a0, a1, a2, a3, aaddr);
#pragma unroll
        for (int nc = 0; nc < NC; nc++) {
            unsigned b0, b1;
            unsigned baddr = smem_u32(&Ws[(kc * 16 + (lane & 15)) * MP + nc * 8]);
            ldsm_x2t(b0, b1, baddr);
            mma16816(acc[nc], a0, a1, a2, a3, b0, b1);
        }
    }

    int rA = rowBase + rw + (lane >> 2);
    int rB = rA + 8;
    int colb = (lane & 3) * 2;
#pragma unroll
    for (int nc = 0; nc < NC; nc++) {
        int col = nc * 8 + colb;
        if (rA < nrows)
            *(__half2*)&Yh[(size_t)rA * M + col] = __floats2half2_rn(acc[nc][0], acc[nc][1]);
        if (rB < nrows)
            *(__half2*)&Yh[(size_t)rB * M + col] = __floats2half2_rn(acc[nc][2], acc[nc][3]);
    }
}

// ----------------------------------------------------- sparse aggregation, M=64
// TWO nodes per warp; lane owns 4 features via one 8B fp16 gather per edge
// (full row = ONE 128B line). fp32 accumulate; fused bias+relu(+residual).
__global__ void agg64_kernel(const __half* __restrict__ suph,
                             const float* __restrict__ bias,
                             float* hout, const float* resid, int has_resid) {
    int gw   = (blockIdx.x * blockDim.x + threadIdx.x) >> 5;
    int lane = threadIdx.x & 31;
    int hf   = lane >> 4, sub = lane & 15;
    int node = gw * 2 + hf;
    if (node >= NNODES) return;
    int e   = g_rowptr[node];
    int end = g_rowptr[node + 1];
    float4 a = make_float4(0.f, 0.f, 0.f, 0.f);
    for (; e + 4 <= end; e += 4) {
        int2 e0 = g_edge[e], e1 = g_edge[e + 1], e2 = g_edge[e + 2], e3 = g_edge[e + 3];
        uint2 r0 = *(const uint2*)&suph[(size_t)e0.x * 64 + sub * 4];
        uint2 r1 = *(const uint2*)&suph[(size_t)e1.x * 64 + sub * 4];
        uint2 r2 = *(const uint2*)&suph[(size_t)e2.x * 64 + sub * 4];
        uint2 r3 = *(const uint2*)&suph[(size_t)e3.x * 64 + sub * 4];
        float w0 = __int_as_float(e0.y), w1 = __int_as_float(e1.y);
        float w2 = __int_as_float(e2.y), w3 = __int_as_float(e3.y);
        float2 fa, fb;
        h4_to_f4(r0, fa, fb);
        a.x = fmaf(fa.x, w0, a.x); a.y = fmaf(fa.y, w0, a.y);
        a.z = fmaf(fb.x, w0, a.z); a.w = fmaf(fb.y, w0, a.w);
        h4_to_f4(r1, fa, fb);
        a.x = fmaf(fa.x, w1, a.x); a.y = fmaf(fa.y, w1, a.y);
        a.z = fmaf(fb.x, w1, a.z); a.w = fmaf(fb.y, w1, a.w);
        h4_to_f4(r2, fa, fb);
        a.x = fmaf(fa.x, w2, a.x); a.y = fmaf(fa.y, w2, a.y);
        a.z = fmaf(fb.x, w2, a.z); a.w = fmaf(fb.y, w2, a.w);
        h4_to_f4(r3, fa, fb);
        a.x = fmaf(fa.x, w3, a.x); a.y = fmaf(fa.y, w3, a.y);
        a.z = fmaf(fb.x, w3, a.z); a.w = fmaf(fb.y, w3, a.w);
    }
    for (; e < end; e++) {
        int2 ed = g_edge[e];
        uint2 rv = *(const uint2*)&suph[(size_t)ed.x * 64 + sub * 4];
        float w = __int_as_float(ed.y);
        float2 fa, fb;
        h4_to_f4(rv, fa, fb);
        a.x = fmaf(fa.x, w, a.x); a.y = fmaf(fa.y, w, a.y);
        a.z = fmaf(fb.x, w, a.z); a.w = fmaf(fb.y, w, a.w);
    }
    float4 bv = ((const float4*)bias)[sub];
    a.x = fmaxf(a.x + bv.x, 0.f);
    a.y = fmaxf(a.y + bv.y, 0.f);
    a.z = fmaxf(a.z + bv.z, 0.f);
    a.w = fmaxf(a.w + bv.w, 0.f);
    if (has_resid) {               // resid may alias hout: same-element RMW only
        float4 rv = ((const float4*)(resid + (size_t)node * 64))[sub];
        a.x += rv.x; a.y += rv.y; a.z += rv.z; a.w += rv.w;
    }
    ((float4*)(hout + (size_t)node * 64))[sub] = a;
}

// ------------------------------------------- sparse aggregation + log_softmax, M=40
__global__ void agg40_kernel(const __half* __restrict__ suph,
                             const float* __restrict__ bias,
                             float* __restrict__ out) {
    int gw   = (blockIdx.x * blockDim.x + threadIdx.x) >> 5;
    int lane = threadIdx.x & 31;
    int hf   = lane >> 4, sub = lane & 15;
    int node = gw * 2 + hf;
    if (node >= NNODES) return;
    const bool act = (sub < 10);
    int e   = g_rowptr[node];
    int end = g_rowptr[node + 1];
    float4 a = make_float4(0.f, 0.f, 0.f, 0.f);
    for (; e + 4 <= end; e += 4) {
        int2 e0 = g_edge[e], e1 = g_edge[e + 1], e2 = g_edge[e + 2], e3 = g_edge[e + 3];
        uint2 r0 = make_uint2(0, 0), r1 = r0, r2 = r0, r3 = r0;
        if (act) {
            r0 = *(const uint2*)&suph[(size_t)e0.x * 40 + sub * 4];
            r1 = *(const uint2*)&suph[(size_t)e1.x * 40 + sub * 4];
            r2 = *(const uint2*)&suph[(size_t)e2.x * 40 + sub * 4];
            r3 = *(const uint2*)&suph[(size_t)e3.x * 40 + sub * 4];
        }
        float w0 = __int_as_float(e0.y), w1 = __int_as_float(e1.y);
        float w2 = __int_as_float(e2.y), w3 = __int_as_float(e3.y);
        float2 fa, fb;
        h4_to_f4(r0, fa, fb);
        a.x = fmaf(fa.x, w0, a.x); a.y = fmaf(fa.y, w0, a.y);
        a.z = fmaf(fb.x, w0, a.z); a.w = fmaf(fb.y, w0, a.w);
        h4_to_f4(r1, fa, fb);
        a.x = fmaf(fa.x, w1, a.x); a.y = fmaf(fa.y, w1, a.y);
        a.z = fmaf(fb.x, w1, a.z); a.w = fmaf(fb.y, w1, a.w);
        h4_to_f4(r2, fa, fb);
        a.x = fmaf(fa.x, w2, a.x); a.y = fmaf(fa.y, w2, a.y);
        a.z = fmaf(fb.x, w2, a.z); a.w = fmaf(fb.y, w2, a.w);
        h4_to_f4(r3, fa, fb);
        a.x = fmaf(fa.x, w3, a.x); a.y = fmaf(fa.y, w3, a.y);
        a.z = fmaf(fb.x, w3, a.z); a.w = fmaf(fb.y, w3, a.w);
    }
    for (; e < end; e++) {
        int2 ed = g_edge[e];
        uint2 rv = make_uint2(0, 0);
        if (act) rv = *(const uint2*)&suph[(size_t)ed.x * 40 + sub * 4];
        float w = __int_as_float(ed.y);
        float2 fa, fb;
        h4_to_f4(rv, fa, fb);
        a.x = fmaf(fa.x, w, a.x); a.y = fmaf(fa.y, w, a.y);
        a.z = fmaf(fb.x, w, a.z); a.w = fmaf(fb.y, w, a.w);
    }
    if (act) {
        float4 bv = ((const float4*)bias)[sub];
        a.x += bv.x; a.y += bv.y; a.z += bv.z; a.w += bv.w;
    }

    // log_softmax over 40 features held by lanes sub<10 (4 each); width-16 reduce
    float m = act ? fmaxf(fmaxf(a.x, a.y), fmaxf(a.z, a.w)) : -3.4e38f;
#pragma unroll
    for (int o = 8; o; o >>= 1) m = fmaxf(m, __shfl_xor_sync(0xffffffffu, m, o, 16));
    float ssum = act ? (__expf(a.x - m) + __expf(a.y - m) +
                        __expf(a.z - m) + __expf(a.w - m)) : 0.f;
#pragma unroll
    for (int o = 8; o; o >>= 1) ssum += __shfl_xor_sync(0xffffffffu, ssum, o, 16);
    float L = m + __logf(ssum);

    if (act) {
        float4 o4; o4.x = a.x - L; o4.y = a.y - L; o4.z = a.z - L; o4.w = a.w - L;
        ((float4*)(out + (size_t)node * 40))[sub] = o4;
    }
}

// ---------------------------------------------------------------- launch
extern "C" void kernel_launch(void* const* d_in, const int* in_sizes, int n_in,
                              void* d_out, int out_size) {
    const float* x   = (const float*)d_in[0];
    const int*   src = (const int*)d_in[1];
    const int*   tgt = (const int*)d_in[2];
    const float* mw  = (const float*)d_in[3];
    const float* W0  = (const float*)d_in[4];  const float* b0 = (const float*)d_in[5];
    const float* W1  = (const float*)d_in[6];  const float* b1 = (const float*)d_in[7];
    const float* W2  = (const float*)d_in[8];  const float* b2 = (const float*)d_in[9];
    const float* W3  = (const float*)d_in[10]; const float* b3 = (const float*)d_in[11];
    float* out = (float*)d_out;

    const int S0 = (128 * 136 + 128 * 72) * 2;   // 53248 (opt-in)
    const int S1 = (128 * 72 + 64 * 72) * 2;     // 27648
    const int S3 = (128 * 72 + 64 * 48) * 2;     // 24576
    cudaFuncSetAttribute(gemm_kernel<128, 64>, cudaFuncAttributeMaxDynamicSharedMemorySize, S0);

    void* p;
    cudaGetSymbolAddress(&p, g_suph);  __half* sup = (__half*)p;
    cudaGetSymbolAddress(&p, g_h);     float*  h   = (float*)p;

    // ---- CSR build (counts zeroed by static init / scanC self-clean) ----
    hist_kernel<<<(NEDGES + 255) / 256, 256>>>(tgt);
    scanA_kernel<<<SCANB, 256>>>();
    scanB_kernel<<<1, 512>>>();
    scanC_kernel<<<SCANB, 256>>>();
    scatter_kernel<<<(NEDGES + 255) / 256, 256>>>(src, tgt, mw);

    const int gblocks  = (NNODES + 127) / 128;
    const int a2blocks = (((NNODES + 1) / 2) * 32 + 255) / 256;   // 2 nodes/warp

    // layer 0: h = relu(A @ (x W0) + b0)
    gemm_kernel<128, 64><<<gblocks, 256, S0>>>(x, W0, sup, NNODES);
    agg64_kernel<<<a2blocks, 256>>>(sup, b0, h, nullptr, 0);
    // layer 1: h = relu(A @ (h W1) + b1) + h
    gemm_kernel<64, 64><<<gblocks, 256, S1>>>(h, W1, sup, NNODES);
    agg64_kernel<<<a2blocks, 256>>>(sup, b1, h, h, 1);
    // layer 2
    gemm_kernel<64, 64><<<gblocks, 256, S1>>>(h, W2, sup, NNODES);
    agg64_kernel<<<a2blocks, 256>>>(sup, b2, h, h, 1);
    // layer 3: out = log_softmax(A @ (h W3) + b3)
    gemm_kernel<64, 40><<<gblocks, 256, S3>>>(h, W3, sup, NNODES);
    agg40_kernel<<<a2blocks, 256>>>(sup, b3, out);
}